// round 4
// baseline (speedup 1.0000x reference)
#include <cuda_runtime.h>
#include <cstdint>

// Problem constants
#define BATCH   8
#define CHANS   32
#define HIN     64
#define WIN     64
#define KS      3
#define HO      62
#define WO      62
#define NCONV   8
#define INFEAT  9      // 3x3
#define NCOEF   8      // grid 5 + order 3
#define NFEAT   9      // 1 silu + 8 basis
#define BAND_R  8      // output rows per block
#define TROWS   10     // input rows per tile (BAND_R + 2)
#define TCOLS   66     // tile width: 64 data + 2 halo cols (read-garbage, masked)
#define PLANE   (TROWS * TCOLS)
#define NTHREADS 128

typedef unsigned long long u64;

__device__ __forceinline__ void fma2(u64 &d, u64 a, u64 b) {
    asm("fma.rn.f32x2 %0, %1, %2, %0;" : "+l"(d) : "l"(a), "l"(b));
}

__device__ __forceinline__ u64 dup2(float v) {
    u64 r;
    asm("mov.b64 %0, {%1, %1};" : "=l"(r) : "f"(v));
    return r;
}

__device__ __forceinline__ float lo32(u64 a) {
    return __uint_as_float((unsigned int)(a & 0xFFFFFFFFULL));
}
__device__ __forceinline__ float hi32(u64 a) {
    return __uint_as_float((unsigned int)(a >> 32));
}

__global__ __launch_bounds__(NTHREADS, 4)
void kan_conv_kernel(const float* __restrict__ x,
                     const float* __restrict__ base_w,
                     const float* __restrict__ spline_w,
                     const float* __restrict__ spline_s,
                     const float* __restrict__ grid,
                     float* __restrict__ out) {
    // SMEM: DUPLICATED feature planes [f][row][col] as {v,v} 64-bit pairs
    __shared__ __align__(16) u64  s_feat[NFEAT * PLANE];        // 9*660*8 = 47520 B
    __shared__ __align__(16) float s_w[NFEAT * INFEAT * NCONV]; // 648 f = 2592 B

    const int tid  = threadIdx.x;
    const int band = blockIdx.x;          // 0..7
    const int img  = blockIdx.y;          // 0..255  (b*32 + c)
    const int y0   = band * BAND_R;       // first output row of band

    // ---- Phase 0a: combined weights into SMEM ----
    // f==0 -> base_weight[n,i]; f==1+s -> spline_w[n,i,s]*scaler[n,i]
    for (int idx = tid; idx < NFEAT * INFEAT * NCONV; idx += NTHREADS) {
        int f    = idx / (INFEAT * NCONV);
        int rest = idx % (INFEAT * NCONV);
        int i    = rest / NCONV;
        int n    = rest % NCONV;
        float v;
        if (f == 0) {
            v = base_w[n * INFEAT + i];
        } else {
            int s = f - 1;
            v = spline_w[(n * INFEAT + i) * NCOEF + s] * spline_s[n * INFEAT + i];
        }
        s_w[idx] = v;
    }

    // ---- Phase 0b: vectorized zero-fill of all 9 dup'd planes ----
    {
        ulonglong2 z2; z2.x = 0ULL; z2.y = 0ULL;
        ulonglong2* zp = (ulonglong2*)s_feat;
        #pragma unroll 4
        for (int i = tid; i < (NFEAT * PLANE) / 2; i += NTHREADS)
            zp[i] = z2;
    }

    // uniform knot grid parameters (read actual values for fp consistency)
    const float g0    = grid[0];
    const float inv_h = 1.0f / (grid[1] - grid[0]);

    __syncthreads();   // zero-fill must complete before scattered basis writes

    // ---- Phase 1: features (silu + 4 nonzero cubic B-spline bases), dup'd ----
    const float* xin = x + img * (HIN * WIN);
    #pragma unroll
    for (int e = tid; e < TROWS * WIN; e += NTHREADS) {
        int row  = e >> 6;          // /64
        int col  = e & 63;
        int y_in = y0 + row;
        float v  = (y_in < HIN) ? xin[y_in * WIN + col] : 0.0f;

        u64* bp = &s_feat[row * TCOLS + col];

        // silu (plane f=0)
        float sig = 1.0f / (1.0f + __expf(-v));
        bp[0] = dup2(v * sig);

        // uniform cubic B-spline: only 4 nonzero bases
        float u  = (v - g0) * inv_h;
        float fj = floorf(u);
        int   j0 = (int)fj;
        float t  = u - fj;
        float t2 = t * t;
        float t3 = t2 * t;
        float omt = 1.0f - t;
        const float s6 = 1.0f / 6.0f;
        float c0 = omt * omt * omt * s6;                            // b3[j0-3]
        float c1 = (3.0f * t3 - 6.0f * t2 + 4.0f) * s6;             // b3[j0-2]
        float c2 = (-3.0f * t3 + 3.0f * t2 + 3.0f * t + 1.0f) * s6; // b3[j0-1]
        float c3 = t3 * s6;                                         // b3[j0]

        int jj;
        jj = j0 - 3; if (jj >= 0 && jj <= 7) bp[(1 + jj) * PLANE] = dup2(c0);
        jj = j0 - 2; if (jj >= 0 && jj <= 7) bp[(1 + jj) * PLANE] = dup2(c1);
        jj = j0 - 1; if (jj >= 0 && jj <= 7) bp[(1 + jj) * PLANE] = dup2(c2);
        jj = j0;     if (jj >= 0 && jj <= 7) bp[(1 + jj) * PLANE] = dup2(c3);
    }
    __syncthreads();

    // ---- Phase 2: 3x3 conv over 9 feature channels -> 8 outputs ----
    // thread -> (output row r in 0..7, 4 consecutive output cols starting at x0)
    const int txq = tid & 15;         // 0..15
    const int r   = tid >> 4;         // 0..7
    const int x0  = txq * 4;          // 0..60
    const int y   = y0 + r;

    u64 acc[4][4];                    // [pixel][n-pair], f32x2 packed over n
    #pragma unroll
    for (int p = 0; p < 4; ++p)
        #pragma unroll
        for (int q = 0; q < 4; ++q)
            acc[p][q] = 0ULL;

    #pragma unroll
    for (int dy = 0; dy < 3; ++dy) {
        #pragma unroll
        for (int f = 0; f < NFEAT; ++f) {
            // dup'd features, 16B-aligned (TCOLS*row + x0 is even)
            const ulonglong2* fp =
                (const ulonglong2*)&s_feat[(f * TROWS + (r + dy)) * TCOLS + x0];
            ulonglong2 a01 = fp[0];
            ulonglong2 a23 = fp[1];
            ulonglong2 a45 = fp[2];
            u64 dv[6];
            dv[0] = a01.x; dv[1] = a01.y; dv[2] = a23.x;
            dv[3] = a23.y; dv[4] = a45.x; dv[5] = a45.y;

            #pragma unroll
            for (int dx = 0; dx < 3; ++dx) {
                const float* wptr = &s_w[(f * INFEAT + dy * 3 + dx) * NCONV];
                ulonglong2 wa = *(const ulonglong2*)(wptr);       // (w0,w1),(w2,w3)
                ulonglong2 wb = *(const ulonglong2*)(wptr + 4);   // (w4,w5),(w6,w7)
                #pragma unroll
                for (int p = 0; p < 4; ++p) {
                    u64 fd = dv[dx + p];
                    fma2(acc[p][0], fd, wa.x);
                    fma2(acc[p][1], fd, wa.y);
                    fma2(acc[p][2], fd, wb.x);
                    fma2(acc[p][3], fd, wb.y);
                }
            }
        }
    }

    // ---- store: out[((img*8 + n)*62 + y)*62 + x], paired STG.64 ----
    if (y < HO) {
        #pragma unroll
        for (int q = 0; q < 4; ++q) {
            float* po_lo = out + ((img * NCONV + 2 * q    ) * HO + y) * WO + x0;
            float* po_hi = out + ((img * NCONV + 2 * q + 1) * HO + y) * WO + x0;
            float2 l01 = make_float2(lo32(acc[0][q]), lo32(acc[1][q]));
            float2 h01 = make_float2(hi32(acc[0][q]), hi32(acc[1][q]));
            *(float2*)po_lo = l01;            // cols x0, x0+1 (always valid)
            *(float2*)po_hi = h01;
            if (x0 < 60) {                    // cols x0+2, x0+3 valid
                float2 l23 = make_float2(lo32(acc[2][q]), lo32(acc[3][q]));
                float2 h23 = make_float2(hi32(acc[2][q]), hi32(acc[3][q]));
                *(float2*)(po_lo + 2) = l23;
                *(float2*)(po_hi + 2) = h23;
            }
        }
    }
}

extern "C" void kernel_launch(void* const* d_in, const int* in_sizes, int n_in,
                              void* d_out, int out_size) {
    const float* x   = (const float*)d_in[0];
    const float* bw  = (const float*)d_in[1];
    const float* sw  = (const float*)d_in[2];
    const float* ss  = (const float*)d_in[3];
    const float* gr  = (const float*)d_in[4];
    float* out = (float*)d_out;

    dim3 grid(8, BATCH * CHANS);   // 8 row-bands x 256 images
    kan_conv_kernel<<<grid, NTHREADS>>>(x, bw, sw, ss, gr, out);
}

// round 5
// speedup vs baseline: 1.3746x; 1.3746x over previous
#include <cuda_runtime.h>
#include <cstdint>

// Problem constants
#define BATCH   8
#define CHANS   32
#define HIN     64
#define WIN     64
#define KS      3
#define HO      62
#define WO      62
#define NCONV   8
#define INFEAT  9      // 3x3
#define NCOEF   8      // grid 5 + order 3
#define NFEAT   9      // 1 silu + 8 basis
#define BAND_R  8      // output rows per block
#define TROWS   10     // input rows per tile (BAND_R + 2)
#define TCOLS   68     // padded tile width (64 data + 4 pad, keeps 16B align)
#define PLANE   (TROWS * TCOLS)
#define NTHREADS 128

typedef unsigned long long u64;

__device__ __forceinline__ void fma2(u64 &d, u64 a, u64 b) {
    asm("fma.rn.f32x2 %0, %1, %2, %0;" : "+l"(d) : "l"(a), "l"(b));
}

__device__ __forceinline__ u64 dup2(float v) {
    u64 r;
    asm("mov.b64 %0, {%1, %1};" : "=l"(r) : "f"(v));
    return r;
}

__device__ __forceinline__ float lo32(u64 a) {
    return __uint_as_float((unsigned int)(a & 0xFFFFFFFFULL));
}
__device__ __forceinline__ float hi32(u64 a) {
    return __uint_as_float((unsigned int)(a >> 32));
}

__global__ __launch_bounds__(NTHREADS, 9)
void kan_conv_kernel(const float* __restrict__ x,
                     const float* __restrict__ base_w,
                     const float* __restrict__ spline_w,
                     const float* __restrict__ spline_s,
                     const float* __restrict__ grid,
                     float* __restrict__ out) {
    // SMEM: feature planes [f][row][col], combined weights [f][i][n]
    __shared__ __align__(16) float s_feat[NFEAT * PLANE];       // 9*680*4 = 24480 B
    __shared__ __align__(16) float s_w[NFEAT * INFEAT * NCONV]; // 648 f = 2592 B

    const int tid  = threadIdx.x;
    const int band = blockIdx.x;          // 0..7
    const int img  = blockIdx.y;          // 0..255  (b*32 + c)
    const int y0   = band * BAND_R;       // first output row of band

    // ---- Phase 0a: combined weights into SMEM ----
    // f==0 -> base_weight[n,i]; f==1+s -> spline_w[n,i,s]*scaler[n,i]
    for (int idx = tid; idx < NFEAT * INFEAT * NCONV; idx += NTHREADS) {
        int f    = idx / (INFEAT * NCONV);
        int rest = idx % (INFEAT * NCONV);
        int i    = rest / NCONV;
        int n    = rest % NCONV;
        float v;
        if (f == 0) {
            v = base_w[n * INFEAT + i];
        } else {
            int s = f - 1;
            v = spline_w[(n * INFEAT + i) * NCOEF + s] * spline_s[n * INFEAT + i];
        }
        s_w[idx] = v;
    }

    // ---- Phase 0b: vectorized zero-fill of the 8 basis planes ----
    {
        float4 z4 = make_float4(0.f, 0.f, 0.f, 0.f);
        float4* zp = (float4*)(s_feat + PLANE);
        #pragma unroll 4
        for (int i = tid; i < (8 * PLANE) / 4; i += NTHREADS)
            zp[i] = z4;
    }

    // uniform knot grid parameters (read actual values for fp consistency)
    const float g0    = grid[0];
    const float inv_h = 1.0f / (grid[1] - grid[0]);

    __syncthreads();   // zero-fill must complete before scattered basis writes

    // ---- Phase 1: features (silu + 4 nonzero cubic B-spline bases) ----
    const float* xin = x + img * (HIN * WIN);
    #pragma unroll
    for (int e = tid; e < TROWS * WIN; e += NTHREADS) {
        int row  = e >> 6;          // /64
        int col  = e & 63;
        int y_in = y0 + row;
        float v  = (y_in < HIN) ? xin[y_in * WIN + col] : 0.0f;

        float* bp = &s_feat[row * TCOLS + col];

        // silu (plane f=0)
        float sig = 1.0f / (1.0f + __expf(-v));
        bp[0] = v * sig;

        // uniform cubic B-spline: only 4 nonzero bases
        float u  = (v - g0) * inv_h;
        float fj = floorf(u);
        int   j0 = (int)fj;
        float t  = u - fj;
        float t2 = t * t;
        float t3 = t2 * t;
        float omt = 1.0f - t;
        const float s6 = 1.0f / 6.0f;
        float c0 = omt * omt * omt * s6;                            // b3[j0-3]
        float c1 = (3.0f * t3 - 6.0f * t2 + 4.0f) * s6;             // b3[j0-2]
        float c2 = (-3.0f * t3 + 3.0f * t2 + 3.0f * t + 1.0f) * s6; // b3[j0-1]
        float c3 = t3 * s6;                                         // b3[j0]

        int jj;
        jj = j0 - 3; if (jj >= 0 && jj <= 7) bp[(1 + jj) * PLANE] = c0;
        jj = j0 - 2; if (jj >= 0 && jj <= 7) bp[(1 + jj) * PLANE] = c1;
        jj = j0 - 1; if (jj >= 0 && jj <= 7) bp[(1 + jj) * PLANE] = c2;
        jj = j0;     if (jj >= 0 && jj <= 7) bp[(1 + jj) * PLANE] = c3;
    }
    __syncthreads();

    // ---- Phase 2: 3x3 conv over 9 feature channels -> 8 outputs ----
    // thread -> (output row r in 0..7, 4 consecutive output cols starting at x0)
    const int txq = tid & 15;         // 0..15
    const int r   = tid >> 4;         // 0..7
    const int x0  = txq * 4;          // 0..60
    const int y   = y0 + r;

    u64 acc[4][4];                    // [pixel][n-pair], f32x2 packed over n
    #pragma unroll
    for (int p = 0; p < 4; ++p)
        #pragma unroll
        for (int q = 0; q < 4; ++q)
            acc[p][q] = 0ULL;

    const float* frow0 = &s_feat[r * TCOLS + x0];

    #pragma unroll
    for (int dy = 0; dy < 3; ++dy) {
        #pragma unroll
        for (int f = 0; f < NFEAT; ++f) {
            const float* fp = frow0 + (f * TROWS + dy) * TCOLS;
            float4 v4 = *(const float4*)fp;        // cols x0..x0+3 (16B aligned)
            float2 v2 = *(const float2*)(fp + 4);  // cols x0+4, x0+5
            u64 dv[6];
            dv[0] = dup2(v4.x); dv[1] = dup2(v4.y); dv[2] = dup2(v4.z);
            dv[3] = dup2(v4.w); dv[4] = dup2(v2.x); dv[5] = dup2(v2.y);

            #pragma unroll
            for (int dx = 0; dx < 3; ++dx) {
                const float* wptr = &s_w[(f * INFEAT + dy * 3 + dx) * NCONV];
                ulonglong2 wa = *(const ulonglong2*)(wptr);       // (w0,w1),(w2,w3)
                ulonglong2 wb = *(const ulonglong2*)(wptr + 4);   // (w4,w5),(w6,w7)
                #pragma unroll
                for (int p = 0; p < 4; ++p) {
                    u64 fd = dv[dx + p];
                    fma2(acc[p][0], fd, wa.x);
                    fma2(acc[p][1], fd, wa.y);
                    fma2(acc[p][2], fd, wb.x);
                    fma2(acc[p][3], fd, wb.y);
                }
            }
        }
    }

    // ---- store: out[((img*8 + n)*62 + y)*62 + x], paired STG.64 ----
    if (y < HO) {
        #pragma unroll
        for (int q = 0; q < 4; ++q) {
            float* po_lo = out + ((img * NCONV + 2 * q    ) * HO + y) * WO + x0;
            float* po_hi = out + ((img * NCONV + 2 * q + 1) * HO + y) * WO + x0;
            float2 l01 = make_float2(lo32(acc[0][q]), lo32(acc[1][q]));
            float2 h01 = make_float2(hi32(acc[0][q]), hi32(acc[1][q]));
            *(float2*)po_lo = l01;            // cols x0, x0+1 (always valid)
            *(float2*)po_hi = h01;
            if (x0 < 60) {                    // cols x0+2, x0+3 valid
                float2 l23 = make_float2(lo32(acc[2][q]), lo32(acc[3][q]));
                float2 h23 = make_float2(hi32(acc[2][q]), hi32(acc[3][q]));
                *(float2*)(po_lo + 2) = l23;
                *(float2*)(po_hi + 2) = h23;
            }
        }
    }
}

extern "C" void kernel_launch(void* const* d_in, const int* in_sizes, int n_in,
                              void* d_out, int out_size) {
    const float* x   = (const float*)d_in[0];
    const float* bw  = (const float*)d_in[1];
    const float* sw  = (const float*)d_in[2];
    const float* ss  = (const float*)d_in[3];
    const float* gr  = (const float*)d_in[4];
    float* out = (float*)d_out;

    dim3 grid(8, BATCH * CHANS);   // 8 row-bands x 256 images
    kan_conv_kernel<<<grid, NTHREADS>>>(x, bw, sw, ss, gr, out);
}